// round 11
// baseline (speedup 1.0000x reference)
#include <cuda_runtime.h>
#include <cstdint>
#include <math_constants.h>

// Problem constants
#define NROWS   131072      // 256*512
#define DDIM    64
#define ECODES  1024
#define CHUNK   64          // codes per chunk (16 cgs x 4 codes)
#define NCHUNK  (ECODES / CHUNK)
#define BLOCK   256
#define RPB     128         // rows per CTA (64 row-pairs)
#define GRID    (NROWS / RPB)

// smem layout (bytes)
#define XP_ULL     (64 * 66)                 // row-pair x: [pair][k], stride 66 ULL
#define XP_BYTES   (XP_ULL * 8)              // 33792
#define WD_ULL     4256                      // dup w, code-major staggered
#define WD_BYTES   (WD_ULL * 8)              // 34048
#define OFF_WD     XP_BYTES
#define OFF_T2     (OFF_WD + WD_BYTES)       // 64 floats
#define OFF_T1     (OFF_T2 + 256)            // 128 floats
#define OFF_IDX    (OFF_T1 + 512)            // 128 ints
#define OFF_RED    (OFF_IDX + 512)           // 256 floats
#define SMEM_BYTES (OFF_RED + 1024)          // 70144

typedef unsigned long long ull;

__device__ float        g_loss_acc;   // zero-init; reset by final CTA each call
__device__ unsigned int g_ctr;        // zero-init; wraps to 0 each call
__device__ float        g_t2[ECODES];

__device__ __forceinline__ ull f32x2_pack(float a, float b) {
    ull r; asm("mov.b64 %0, {%1, %2};" : "=l"(r) : "f"(a), "f"(b)); return r;
}
__device__ __forceinline__ void f32x2_unpack(ull v, float& a, float& b) {
    asm("mov.b64 {%0, %1}, %2;" : "=f"(a), "=f"(b) : "l"(v));
}
__device__ __forceinline__ ull f32x2_fma(ull a, ull b, ull c) {
    ull r; asm("fma.rn.f32x2 %0, %1, %2, %3;" : "=l"(r) : "l"(a), "l"(b), "l"(c)); return r;
}

// dup-w smem offset for code c, k (ULL units): code-major, stagger 2 ULL per 4 codes
__device__ __forceinline__ int wd_off(int c, int k) {
    return c * 66 + 2 * (c >> 2) + k;
}

// ---- prep: t2[c] = sum_k fl(w[c][k]^2), sequential adds ----
__global__ __launch_bounds__(256) void vq_prep_kernel(const float* __restrict__ wt) {
    int c = blockIdx.x * blockDim.x + threadIdx.x;
    if (c < ECODES) {
        const float* wr = wt + (size_t)c * DDIM;
        float s = 0.0f;
        #pragma unroll
        for (int k = 0; k < DDIM; k++)
            s = __fadd_rn(s, __fmul_rn(wr[k], wr[k]));
        g_t2[c] = s;
    }
}

// ---- main: row-pair tiled distances + argmin + outputs + loss finalize ----
__global__ __launch_bounds__(BLOCK, 3) void vq_main_kernel(
    const float* __restrict__ inp,   // [131072, 64]
    const float* __restrict__ wt,    // [1024, 64]
    float* out_q,                    // [131072, 64] or null
    float* out_enc,                  // [131072, 1024] or null (only 4B-aligned)
    float* out_loss)                 // [1] or null
{
    extern __shared__ __align__(16) char smem_raw[];
    ull*   xp    = reinterpret_cast<ull*>(smem_raw);               // [64 pairs][66]
    ull*   wd    = reinterpret_cast<ull*>(smem_raw + OFF_WD);      // dup w
    float* t2sh  = reinterpret_cast<float*>(smem_raw + OFF_T2);    // [64]
    float* t1sh  = reinterpret_cast<float*>(smem_raw + OFF_T1);    // [128]
    int*   idx_sh= reinterpret_cast<int*>(smem_raw + OFF_IDX);     // [128]
    float* red   = reinterpret_cast<float*>(smem_raw + OFF_RED);   // [256]

    const int tid = threadIdx.x;
    const int pg  = tid >> 4;        // 0..15 : pair group (4 pairs: pg+16j)
    const int cg  = tid & 15;        // 0..15 : code group (4 codes per chunk)
    const size_t rowbase = (size_t)blockIdx.x * RPB;

    // ---- stage x as row-pair ULLs: xp[pair][k] = (x[2p][k], x[2p+1][k]) ----
    {
        const float* gx = inp + rowbase * DDIM;
        float* xpf = reinterpret_cast<float*>(xp);
        for (int i = tid; i < RPB * DDIM; i += BLOCK) {
            int row = i >> 6, k = i & 63;
            // float index: ((row>>1)*66 + k)*2 + (row&1)
            xpf[(((row >> 1) * 66 + k) << 1) + (row & 1)] = gx[i];
        }
    }
    __syncthreads();

    // ---- t1 per row into smem: sequential fl(x^2) adds, k ascending ----
    if (tid < RPB) {
        const float* xpf = reinterpret_cast<const float*>(xp);
        const int p = tid >> 1, h = tid & 1;
        float s = 0.0f;
        #pragma unroll
        for (int k = 0; k < DDIM; k++) {
            float xv = xpf[((p * 66 + k) << 1) + h];
            s = __fadd_rn(s, __fmul_rn(xv, xv));
        }
        t1sh[tid] = s;
    }

    float best[8]; int bidx[8];
    #pragma unroll
    for (int r = 0; r < 8; r++) { best[r] = CUDART_INF_F; bidx[r] = 0; }

    for (int ch = 0; ch < NCHUNK; ch++) {
        __syncthreads();
        // stage dup w: wd[c][k] = (w[cb+c][k], w[cb+c][k]); coalesced gmem reads
        {
            const float* wg = wt + (size_t)ch * CHUNK * DDIM;
            #pragma unroll 4
            for (int t = 0; t < 16; t++) {
                int idx = tid + t * BLOCK;
                int c = idx >> 6, k = idx & 63;
                float v = wg[(c << 6) + k];
                wd[wd_off(c, k)] = f32x2_pack(v, v);
            }
            if (tid < CHUNK) t2sh[tid] = g_t2[ch * CHUNK + tid];
        }
        __syncthreads();

        ull acc[4][4];
        #pragma unroll
        for (int j = 0; j < 4; j++)
            #pragma unroll
            for (int c = 0; c < 4; c++) acc[j][c] = 0ull;

        const ull* wbase = wd + wd_off(cg * 4, 0);
        #pragma unroll 1
        for (int kp = 0; kp < DDIM / 2; kp++) {
            const int k0 = 2 * kp;
            // w: 4 codes, ulonglong2 = dup(w,k0), dup(w,k1)
            ull w0[4], w1[4];
            #pragma unroll
            for (int c = 0; c < 4; c++) {
                ulonglong2 wv = *reinterpret_cast<const ulonglong2*>(
                    wbase + c * 66 + k0);      // codes cg*4..cg*4+3 share (c>>2) stagger
                w0[c] = wv.x; w1[c] = wv.y;
            }
            #pragma unroll
            for (int j = 0; j < 4; j++) {
                ulonglong2 xv = *reinterpret_cast<const ulonglong2*>(
                    xp + (pg + 16 * j) * 66 + k0);
                #pragma unroll
                for (int c = 0; c < 4; c++)
                    acc[j][c] = f32x2_fma(xv.x, w0[c], acc[j][c]);   // k0
                #pragma unroll
                for (int c = 0; c < 4; c++)
                    acc[j][c] = f32x2_fma(xv.y, w1[c], acc[j][c]);   // k1
            }
        }

        // epilogue: distances + running argmin (codes ascend; strict '<' => first idx)
        const int cbase = ch * CHUNK + cg * 4;
        #pragma unroll
        for (int j = 0; j < 4; j++) {
            const int pr = pg + 16 * j;
            float tA = t1sh[2 * pr], tB = t1sh[2 * pr + 1];
            #pragma unroll
            for (int c = 0; c < 4; c++) {
                float dA, dB; f32x2_unpack(acc[j][c], dA, dB);
                float t2v = t2sh[cg * 4 + c];
                float distA = __fsub_rn(__fadd_rn(tA, t2v), __fmul_rn(2.0f, dA));
                if (distA < best[2 * j])     { best[2 * j]     = distA; bidx[2 * j]     = cbase + c; }
                float distB = __fsub_rn(__fadd_rn(tB, t2v), __fmul_rn(2.0f, dB));
                if (distB < best[2 * j + 1]) { best[2 * j + 1] = distB; bidx[2 * j + 1] = cbase + c; }
            }
        }
    }

    // ---- cross-thread argmin over 16 code-groups (width-16 shuffle) ----
    #pragma unroll
    for (int r = 0; r < 8; r++) {
        float d = best[r]; int ix = bidx[r];
        #pragma unroll
        for (int off = 1; off < 16; off <<= 1) {
            float d2 = __shfl_xor_sync(0xffffffffu, d, off, 16);
            int   i2 = __shfl_xor_sync(0xffffffffu, ix, off, 16);
            if (d2 < d || (d2 == d && i2 < ix)) { d = d2; ix = i2; }
        }
        best[r] = d; bidx[r] = ix;
    }
    if (cg == 0) {
        #pragma unroll
        for (int j = 0; j < 4; j++) {
            const int pr = pg + 16 * j;
            idx_sh[2 * pr]     = bidx[2 * j];
            idx_sh[2 * pr + 1] = bidx[2 * j + 1];
        }
    }

    // ---- zero encodings (alignment-safe: peel to 16B, vector body, tail) ----
    if (out_enc) {
        float* ebase = out_enc + rowbase * (size_t)ECODES;
        const int total = RPB * ECODES;
        const int head = (int)(((16u - ((uintptr_t)ebase & 15u)) & 15u) >> 2);
        if (tid < head) ebase[tid] = 0.0f;
        float4* v = reinterpret_cast<float4*>(ebase + head);
        const int nvec = (total - head) >> 2;
        float4 z = make_float4(0.f, 0.f, 0.f, 0.f);
        for (int i = tid; i < nvec; i += BLOCK) v[i] = z;
        const int tail_start = head + (nvec << 2);
        if (tid < total - tail_start) ebase[tail_start + tid] = 0.0f;
    }
    __syncthreads();   // idx_sh visible + zeros done before scatter

    if (out_enc && tid < RPB)
        out_enc[(rowbase + tid) * (size_t)ECODES + (size_t)idx_sh[tid]] = 1.0f;

    // ---- quantized_st + loss partial ----
    float part = 0.0f;
    for (int i = tid; i < RPB * DDIM; i += BLOCK) {
        int r = i >> 6, k = i & 63;
        float q  = wt[(size_t)idx_sh[r] * DDIM + k];
        float xv = inp[(rowbase + r) * DDIM + k];
        float dqx = __fsub_rn(q, xv);
        part = __fadd_rn(part, __fmul_rn(dqx, dqx));
        if (out_q)
            out_q[rowbase * DDIM + i] = __fadd_rn(xv, dqx);
    }
    red[tid] = part;
    __syncthreads();
    for (int s = BLOCK / 2; s > 0; s >>= 1) {
        if (tid < s) red[tid] += red[tid + s];
        __syncthreads();
    }

    // ---- loss accumulate + last-CTA finalize ----
    if (tid == 0) {
        atomicAdd(&g_loss_acc, red[0]);
        __threadfence();
        unsigned int done = atomicAdd(&g_ctr, 1u);
        if (done == GRID - 1) {
            float m = *((volatile float*)&g_loss_acc) / 8388608.0f;
            if (out_loss) out_loss[0] = __fadd_rn(m, __fmul_rn(0.25f, m));
            g_loss_acc = 0.0f;    // restore state for next (graph-replayed) call
            __threadfence();
            g_ctr = 0u;
        }
    }
}

extern "C" void kernel_launch(void* const* d_in, const int* in_sizes, int n_in,
                              void* d_out, int out_size)
{
    const float* inp = nullptr;
    const float* wt  = nullptr;
    for (int i = 0; i < n_in; i++) {
        if (in_sizes[i] == 8388608) inp = (const float*)d_in[i];
        else if (in_sizes[i] == 65536) wt = (const float*)d_in[i];
    }
    if (!inp || !wt) return;

    float* out = (float*)d_out;
    const long long Q = 8388608LL, ENC = 134217728LL;
    long long os = (long long)out_size;

    float* oL = nullptr; float* oQ = nullptr; float* oE = nullptr;
    if (os == 1 + Q + ENC)      { oL = out; oQ = out + 1; oE = out + 1 + Q; }
    else if (os == Q + ENC)     { oQ = out; oE = out + Q; }
    else if (os == ENC)         { oE = out; }
    else if (os == Q)           { oQ = out; }
    else if (os == 1)           { oL = out; }
    else {
        oL = out;
        if (os >= 1 + Q) oQ = out + 1;
        if (os >= 1 + Q + ENC) oE = out + 1 + Q;
    }

    cudaFuncSetAttribute(vq_main_kernel,
                         cudaFuncAttributeMaxDynamicSharedMemorySize, SMEM_BYTES);

    vq_prep_kernel<<<(ECODES + 255) / 256, 256>>>(wt);
    vq_main_kernel<<<GRID, BLOCK, SMEM_BYTES>>>(inp, wt, oQ, oE, oL);
}

// round 12
// speedup vs baseline: 1.0809x; 1.0809x over previous
#include <cuda_runtime.h>
#include <cstdint>
#include <math_constants.h>

// Problem constants
#define NROWS   131072      // 256*512
#define DDIM    64
#define ECODES  1024
#define CHUNK   128         // codes per chunk
#define NCHUNK  (ECODES / CHUNK)
#define BLOCK   256
#define RPB     128         // rows per CTA
#define GRID    (NROWS / RPB)

// smem layout
#define XD_STRIDE 66                    // ULL per row slot (64 data + 2 pad), 528B
#define XD_ULL    (RPB * XD_STRIDE)     // 8448 ULL = 67584 B
#define WQ_KSTRIDE 81                   // quads (16B) per k-pair row: 16 cg * 5 + 1 pad
#define WQ_QUADS  (32 * WQ_KSTRIDE)     // 2592 quads = 41472 B
#define OFF_WQ    (XD_ULL * 8)
#define OFF_T2    (OFF_WQ + WQ_QUADS * 16)   // 128 floats
#define OFF_T1    (OFF_T2 + 512)             // 128 floats
#define OFF_IDX   (OFF_T1 + 512)             // 128 ints
#define OFF_RED   (OFF_IDX + 512)            // 256 floats
#define SMEM_BYTES (OFF_RED + 1024)

typedef unsigned long long ull;

__device__ float        g_loss_acc;   // zero-init; reset by final CTA each call
__device__ unsigned int g_ctr;        // zero-init; wraps to 0 each call
__device__ float        g_t2[ECODES];

__device__ __forceinline__ ull f32x2_pack(float a, float b) {
    ull r; asm("mov.b64 %0, {%1, %2};" : "=l"(r) : "f"(a), "f"(b)); return r;
}
__device__ __forceinline__ void f32x2_unpack(ull v, float& a, float& b) {
    asm("mov.b64 {%0, %1}, %2;" : "=f"(a), "=f"(b) : "l"(v));
}
__device__ __forceinline__ ull f32x2_fma(ull a, ull b, ull c) {
    ull r; asm("fma.rn.f32x2 %0, %1, %2, %3;" : "=l"(r) : "l"(a), "l"(b), "l"(c)); return r;
}

// ---- prep: t2[c] = sum_k fl(w[c][k]^2), sequential adds ----
__global__ __launch_bounds__(256) void vq_prep_kernel(const float* __restrict__ wt) {
    int c = blockIdx.x * blockDim.x + threadIdx.x;
    if (c < ECODES) {
        const float* wr = wt + (size_t)c * DDIM;
        float s = 0.0f;
        #pragma unroll
        for (int k = 0; k < DDIM; k++)
            s = __fadd_rn(s, __fmul_rn(wr[k], wr[k]));
        g_t2[c] = s;
    }
}

// ---- main: 8x8 register tile, k-pair-packed w, all outputs + loss finalize ----
__global__ __launch_bounds__(BLOCK, 2) void vq_main_kernel(
    const float* __restrict__ inp,   // [131072, 64]
    const float* __restrict__ wt,    // [1024, 64]
    float* out_q,                    // [131072, 64] or null
    float* out_enc,                  // [131072, 1024] or null (only 4B-aligned)
    float* out_loss)                 // [1] or null
{
    extern __shared__ __align__(16) char smem_raw[];
    ull*   xdup  = reinterpret_cast<ull*>(smem_raw);                 // [128 slots][66] (x,x)
    float* wqf   = reinterpret_cast<float*>(smem_raw + OFF_WQ);      // quad-packed w
    float* t2sh  = reinterpret_cast<float*>(smem_raw + OFF_T2);      // [128]
    float* t1sh  = reinterpret_cast<float*>(smem_raw + OFF_T1);      // [128]
    int*   idx_sh= reinterpret_cast<int*>(smem_raw + OFF_IDX);       // [128]
    float* red   = reinterpret_cast<float*>(smem_raw + OFF_RED);     // [256]

    const int tid = threadIdx.x;
    const int rg  = tid >> 4;        // 0..15 : row group (8 rows)
    const int cg  = tid & 15;        // 0..15 : code group (8 codes = 4 code-pairs)
    const size_t rowbase = (size_t)blockIdx.x * RPB;

    // ---- stage x duplicated as (x,x) pairs, permuted: row -> slot = (row>>3) + (row&7)*16 ----
    {
        const float* gx = inp + rowbase * DDIM;
        for (int i = tid; i < RPB * DDIM; i += BLOCK) {
            int row = i >> 6, k = i & 63;
            int slot = (row >> 3) + (row & 7) * 16;
            float v = gx[i];
            xdup[slot * XD_STRIDE + k] = f32x2_pack(v, v);
        }
    }
    __syncthreads();

    // ---- t1 per row into smem: sequential fl(x^2) adds, k ascending ----
    if (tid < RPB) {
        const int slot = (tid >> 3) + (tid & 7) * 16;
        const float* xr = reinterpret_cast<const float*>(xdup + slot * XD_STRIDE);
        float s = 0.0f;
        #pragma unroll
        for (int k = 0; k < DDIM; k++) {
            float xv = xr[2 * k];                 // low lane of (x,x)
            s = __fadd_rn(s, __fmul_rn(xv, xv));
        }
        t1sh[tid] = s;
    }

    float best[8]; int bidx[8];
    #pragma unroll
    for (int r = 0; r < 8; r++) { best[r] = CUDART_INF_F; bidx[r] = 0; }

    for (int ch = 0; ch < NCHUNK; ch++) {
        __syncthreads();
        // stage w quad-packed: element (c_abs, k) ->
        //   quad (kp = k>>1, cgq = c_abs>>3, cq = (c_abs>>1)&3), lane (k&1)*2 + (c_abs&1)
        {
            const float* wg = wt + (size_t)ch * CHUNK * DDIM;
            for (int i = tid; i < CHUNK * DDIM; i += BLOCK) {
                int c = i >> 6, k = i & 63;
                int q = (k >> 1) * WQ_KSTRIDE + (c >> 3) * 5 + ((c >> 1) & 3);
                wqf[q * 4 + (k & 1) * 2 + (c & 1)] = wg[i];
            }
            if (tid < CHUNK) t2sh[tid] = g_t2[ch * CHUNK + tid];
        }
        __syncthreads();

        ull acc[8][4];
        #pragma unroll
        for (int r = 0; r < 8; r++)
            #pragma unroll
            for (int p = 0; p < 4; p++) acc[r][p] = 0ull;

        const ulonglong2* wqbase =
            reinterpret_cast<const ulonglong2*>(wqf) + cg * 5;
        const ull* xbase = xdup + rg * XD_STRIDE;   // slots rg + r*16

        #pragma unroll 2
        for (int kp = 0; kp < DDIM / 2; kp++) {
            // one LDS.128 per code-pair: .x = (w2cp,k0 , w2cp+1,k0), .y = same for k1
            ulonglong2 wv[4];
            #pragma unroll
            for (int p = 0; p < 4; p++)
                wv[p] = wqbase[kp * WQ_KSTRIDE + p];

            #pragma unroll
            for (int r = 0; r < 8; r++) {
                ulonglong2 xv = *reinterpret_cast<const ulonglong2*>(
                    xbase + r * 16 * XD_STRIDE + 2 * kp);
                #pragma unroll
                for (int p = 0; p < 4; p++)
                    acc[r][p] = f32x2_fma(xv.x, wv[p].x, acc[r][p]);   // k0
                #pragma unroll
                for (int p = 0; p < 4; p++)
                    acc[r][p] = f32x2_fma(xv.y, wv[p].y, acc[r][p]);   // k1
            }
        }

        // epilogue: distances + running argmin (codes ascend; strict '<' => first idx)
        const int cbase = ch * CHUNK + cg * 8;
        #pragma unroll
        for (int r = 0; r < 8; r++) {
            float t1v = t1sh[rg * 8 + r];
            float b = best[r]; int bi = bidx[r];
            #pragma unroll
            for (int p = 0; p < 4; p++) {
                float d0, d1; f32x2_unpack(acc[r][p], d0, d1);
                float u0 = __fadd_rn(t1v, t2sh[cg * 8 + 2 * p]);
                float dist0 = __fsub_rn(u0, __fmul_rn(2.0f, d0));
                if (dist0 < b) { b = dist0; bi = cbase + 2 * p; }
                float u1 = __fadd_rn(t1v, t2sh[cg * 8 + 2 * p + 1]);
                float dist1 = __fsub_rn(u1, __fmul_rn(2.0f, d1));
                if (dist1 < b) { b = dist1; bi = cbase + 2 * p + 1; }
            }
            best[r] = b; bidx[r] = bi;
        }
    }

    // ---- cross-thread argmin over the 16 code-groups (width-16 shuffle) ----
    #pragma unroll
    for (int r = 0; r < 8; r++) {
        float d = best[r]; int ix = bidx[r];
        #pragma unroll
        for (int off = 1; off < 16; off <<= 1) {
            float d2 = __shfl_xor_sync(0xffffffffu, d, off, 16);
            int   i2 = __shfl_xor_sync(0xffffffffu, ix, off, 16);
            if (d2 < d || (d2 == d && i2 < ix)) { d = d2; ix = i2; }
        }
        if (cg == 0) idx_sh[rg * 8 + r] = ix;
    }

    // ---- zero encodings (alignment-safe: peel to 16B, vector body, tail) ----
    if (out_enc) {
        float* ebase = out_enc + rowbase * (size_t)ECODES;
        const int total = RPB * ECODES;
        const int head = (int)(((16u - ((uintptr_t)ebase & 15u)) & 15u) >> 2);
        if (tid < head) ebase[tid] = 0.0f;
        float4* v = reinterpret_cast<float4*>(ebase + head);
        const int nvec = (total - head) >> 2;
        float4 z = make_float4(0.f, 0.f, 0.f, 0.f);
        for (int i = tid; i < nvec; i += BLOCK) v[i] = z;
        const int tail_start = head + (nvec << 2);
        if (tid < total - tail_start) ebase[tail_start + tid] = 0.0f;
    }
    __syncthreads();   // idx_sh visible + zeros done before scatter

    if (out_enc && tid < RPB)
        out_enc[(rowbase + tid) * (size_t)ECODES + (size_t)idx_sh[tid]] = 1.0f;

    // ---- quantized_st + loss partial ----
    float part = 0.0f;
    for (int i = tid; i < RPB * DDIM; i += BLOCK) {
        int r = i >> 6, k = i & 63;
        float q  = wt[(size_t)idx_sh[r] * DDIM + k];
        float xv = inp[(rowbase + r) * DDIM + k];
        float dqx = __fsub_rn(q, xv);
        part = __fadd_rn(part, __fmul_rn(dqx, dqx));
        if (out_q)
            out_q[rowbase * DDIM + i] = __fadd_rn(xv, dqx);
    }
    red[tid] = part;
    __syncthreads();
    for (int s = BLOCK / 2; s > 0; s >>= 1) {
        if (tid < s) red[tid] += red[tid + s];
        __syncthreads();
    }

    // ---- loss accumulate + last-CTA finalize ----
    if (tid == 0) {
        atomicAdd(&g_loss_acc, red[0]);
        __threadfence();
        unsigned int done = atomicAdd(&g_ctr, 1u);
        if (done == GRID - 1) {
            float m = *((volatile float*)&g_loss_acc) / 8388608.0f;
            if (out_loss) out_loss[0] = __fadd_rn(m, __fmul_rn(0.25f, m));
            g_loss_acc = 0.0f;    // restore state for next (graph-replayed) call
            __threadfence();
            g_ctr = 0u;
        }
    }
}

extern "C" void kernel_launch(void* const* d_in, const int* in_sizes, int n_in,
                              void* d_out, int out_size)
{
    const float* inp = nullptr;
    const float* wt  = nullptr;
    for (int i = 0; i < n_in; i++) {
        if (in_sizes[i] == 8388608) inp = (const float*)d_in[i];
        else if (in_sizes[i] == 65536) wt = (const float*)d_in[i];
    }
    if (!inp || !wt) return;

    float* out = (float*)d_out;
    const long long Q = 8388608LL, ENC = 134217728LL;
    long long os = (long long)out_size;

    float* oL = nullptr; float* oQ = nullptr; float* oE = nullptr;
    if (os == 1 + Q + ENC)      { oL = out; oQ = out + 1; oE = out + 1 + Q; }
    else if (os == Q + ENC)     { oQ = out; oE = out + Q; }
    else if (os == ENC)         { oE = out; }
    else if (os == Q)           { oQ = out; }
    else if (os == 1)           { oL = out; }
    else {
        oL = out;
        if (os >= 1 + Q) oQ = out + 1;
        if (os >= 1 + Q + ENC) oE = out + 1 + Q;
    }

    cudaFuncSetAttribute(vq_main_kernel,
                         cudaFuncAttributeMaxDynamicSharedMemorySize, SMEM_BYTES);

    vq_prep_kernel<<<(ECODES + 255) / 256, 256>>>(wt);
    vq_main_kernel<<<GRID, BLOCK, SMEM_BYTES>>>(inp, wt, oQ, oE, oL);
}